// round 9
// baseline (speedup 1.0000x reference)
#include <cuda_runtime.h>
#include <math.h>

// Problem constants
#define BB 16
#define NFF 16
#define NN 1024
#define DD 128
#define SS 8
#define HH 128
#define NCHUNK 8

#define SCALE_F 0.08838834764831845f
#define EPS_F 1e-8f

typedef unsigned long long u64;

// ---------------- packed f32x2 helpers (Blackwell FFMA2 path) --------------
__device__ __forceinline__ u64 pack2(float lo, float hi) {
    u64 r;
    asm("mov.b64 %0, {%1, %2};" : "=l"(r)
        : "r"(__float_as_uint(lo)), "r"(__float_as_uint(hi)));
    return r;
}
__device__ __forceinline__ void unpack2(u64 v, float& lo, float& hi) {
    unsigned int a, b;
    asm("mov.b64 {%0, %1}, %2;" : "=r"(a), "=r"(b) : "l"(v));
    lo = __uint_as_float(a); hi = __uint_as_float(b);
}
__device__ __forceinline__ u64 ffma2(u64 a, u64 b, u64 c) {
    u64 d;
    asm("fma.rn.f32x2 %0, %1, %2, %3;" : "=l"(d) : "l"(a), "l"(b), "l"(c));
    return d;
}

// ---------------- scratch (device globals; no allocation allowed) ----------
__device__ float g_k[BB * NFF * NN * DD];                 // 134 MB
__device__ float g_v[BB * NFF * NN * DD];                 // 134 MB
__device__ float g_slots[2][BB * SS * DD];
__device__ float g_upd_part[BB * NCHUNK * SS * DD];       // per-(b,chunk) partial attn@v
__device__ float g_rs_part[BB * NCHUNK * SS];             // per-(b,chunk) partial rowsums

// ---------------------------------------------------------------------------
__device__ __forceinline__ float warp_sum(float v) {
#pragma unroll
    for (int o = 16; o > 0; o >>= 1) v += __shfl_xor_sync(0xffffffffu, v, o);
    return v;
}

// ---------------- init: broadcast slots_init to all batches ----------------
__global__ void sa_init_kernel(const float* __restrict__ slots_init) {
    int idx = blockIdx.x * blockDim.x + threadIdx.x;
    if (idx < BB * SS * DD) g_slots[0][idx] = slots_init[idx & (SS * DD - 1)];
}

// ---------------- kv projection: LN(x) @ [Wk^T | Wv^T] + bias --------------
// Block: 64 rows x 256 cols (k cols 0..127, v cols 128..255). 256 threads.
__global__ __launch_bounds__(256, 1) void sa_kv_kernel(
    const float* __restrict__ x,
    const float* __restrict__ Wk, const float* __restrict__ bk,
    const float* __restrict__ Wv, const float* __restrict__ bv,
    const float* __restrict__ gin, const float* __restrict__ bin) {
    extern __shared__ float sm[];
    float* Wt  = sm;                    // [128][260]  (W transposed: [k][col])
    float* Xs  = Wt + 128 * 260;        // [64][132]   (LN'd input rows)
    float* ms  = Xs + 64 * 132;         // [64]
    float* iss = ms + 64;               // [64]
    float* gs  = iss + 64;              // [128]
    float* bs  = gs + 128;              // [128]
    float* bias = bs + 128;             // [256]

    const int tid = threadIdx.x;
    const int row0 = blockIdx.x * 64;

    // load weights transposed into smem
#pragma unroll 1
    for (int j = 0; j < 32; j++) {
        int idx4 = tid + j * 256;              // 8192 float4
        int outc = idx4 >> 5;
        int in0 = (idx4 & 31) * 4;
        const float* src = (outc < 128) ? (Wk + outc * 128 + in0)
                                        : (Wv + (outc - 128) * 128 + in0);
        float4 w = *(const float4*)src;
        Wt[(in0 + 0) * 260 + outc] = w.x;
        Wt[(in0 + 1) * 260 + outc] = w.y;
        Wt[(in0 + 2) * 260 + outc] = w.z;
        Wt[(in0 + 3) * 260 + outc] = w.w;
    }
    if (tid < 128) { gs[tid] = gin[tid]; bs[tid] = bin[tid]; }
    bias[tid] = (tid < 128) ? bk[tid] : bv[tid - 128];

    // load 64 input rows
#pragma unroll 1
    for (int j = 0; j < 8; j++) {
        int idx4 = tid + j * 256;              // 2048 float4
        int r = idx4 >> 5;
        int c4 = (idx4 & 31) * 4;
        float4 v = *(const float4*)(x + (size_t)(row0 + r) * DD + c4);
        *(float4*)&Xs[r * 132 + c4] = v;
    }
    __syncthreads();

    // per-row LN stats
    if (tid < 64) {
        float s1 = 0.f, s2 = 0.f;
#pragma unroll 16
        for (int i = 0; i < 128; i++) {
            float v = Xs[tid * 132 + i];
            s1 += v; s2 += v * v;
        }
        float m = s1 * (1.f / 128.f);
        float var = s2 * (1.f / 128.f) - m * m;
        ms[tid] = m;
        iss[tid] = rsqrtf(var + 1e-5f);
    }
    __syncthreads();

    // apply LN in place
#pragma unroll 1
    for (int j = 0; j < 8; j++) {
        int idx4 = tid + j * 256;
        int r = idx4 >> 5;
        int c4 = (idx4 & 31) * 4;
        float m = ms[r], is = iss[r];
        float4 v = *(float4*)&Xs[r * 132 + c4];
        v.x = (v.x - m) * is * gs[c4 + 0] + bs[c4 + 0];
        v.y = (v.y - m) * is * gs[c4 + 1] + bs[c4 + 1];
        v.z = (v.z - m) * is * gs[c4 + 2] + bs[c4 + 2];
        v.w = (v.w - m) * is * gs[c4 + 3] + bs[c4 + 3];
        *(float4*)&Xs[r * 132 + c4] = v;
    }
    __syncthreads();

    // register-tiled GEMM: thread = (ty,tx) -> 4 rows x 16 cols.
    // Packed f32x2 (FFMA2): accumulators are 8 u64 pairs per row = 16 cols.
    const int tx = tid & 15, ty = tid >> 4;
    u64 acc2[4][8];
#pragma unroll
    for (int j2 = 0; j2 < 8; j2++) {
        u64 bpair = pack2(bias[tx * 16 + 2 * j2], bias[tx * 16 + 2 * j2 + 1]);
#pragma unroll
        for (int i = 0; i < 4; i++) acc2[i][j2] = bpair;
    }

#pragma unroll 8
    for (int k = 0; k < 128; k++) {
        u64 av2[4];
#pragma unroll
        for (int i = 0; i < 4; i++) {
            float a = Xs[(ty * 4 + i) * 132 + k];
            av2[i] = pack2(a, a);
        }
        u64 wv2[8];
#pragma unroll
        for (int g = 0; g < 4; g++) {
            ulonglong2 p = *(const ulonglong2*)&Wt[k * 260 + tx * 16 + g * 4];
            wv2[g * 2 + 0] = p.x;
            wv2[g * 2 + 1] = p.y;
        }
#pragma unroll
        for (int i = 0; i < 4; i++)
#pragma unroll
            for (int j2 = 0; j2 < 8; j2++)
                acc2[i][j2] = ffma2(av2[i], wv2[j2], acc2[i][j2]);
    }

    // store
#pragma unroll
    for (int i = 0; i < 4; i++) {
        int r = row0 + ty * 4 + i;
#pragma unroll
        for (int g = 0; g < 4; g++) {
            int c = tx * 16 + g * 4;
            float a0, a1, a2, a3;
            unpack2(acc2[i][2 * g + 0], a0, a1);
            unpack2(acc2[i][2 * g + 1], a2, a3);
            float4 o = make_float4(a0, a1, a2, a3);
            if (c < 128) *(float4*)&g_k[(size_t)r * DD + c] = o;
            else         *(float4*)&g_v[(size_t)r * DD + (c - 128)] = o;
        }
    }
}

// ---------------- per-step: q-proj + dots + softmax + attn + updates -------
// grid (NCHUNK=8, B=16), 256 threads (8 warps). Block = (b, 128-n chunk).
__global__ __launch_bounds__(256, 1) void sa_attn_kernel(
    int cur, int frame, int fo, float* __restrict__ outbuf,
    const float* __restrict__ Wq, const float* __restrict__ bq,
    const float* __restrict__ gsl, const float* __restrict__ bsl) {
    extern __shared__ float sm[];
    float* Wqs  = sm;                    // [128][129]
    float* bqs  = Wqs + 128 * 129;       // [128]
    float* gss  = bqs + 128;             // [128]
    float* bss  = gss + 128;             // [128]
    float* sln  = bss + 128;             // [8][128]
    float* q_s  = sln + 1024;            // [8][128]
    float* wacc = q_s + 1024;            // [8 warps][1024]
    float* wrs  = wacc + 8192;           // [8 warps][8]

    const int tid = threadIdx.x;
    const int b = blockIdx.y, chunk = blockIdx.x;
    const int w = tid >> 5, l = tid & 31;
    const float* slots = g_slots[cur];

    // phase 1: stage Wq + params
#pragma unroll 1
    for (int j = 0; j < 16; j++) {
        int idx4 = tid + j * 256;          // 4096 float4
        int o = idx4 >> 5;
        int i0 = (idx4 & 31) * 4;
        float4 wv = *(const float4*)(Wq + o * 128 + i0);
        Wqs[o * 129 + i0 + 0] = wv.x;
        Wqs[o * 129 + i0 + 1] = wv.y;
        Wqs[o * 129 + i0 + 2] = wv.z;
        Wqs[o * 129 + i0 + 3] = wv.w;
    }
    if (tid < 128) { bqs[tid] = bq[tid]; gss[tid] = gsl[tid]; bss[tid] = bsl[tid]; }
    __syncthreads();

    // phase 2: LN slots -> sln  (warp w handles slot s=w)
    {
        const float* row = slots + (b * SS + w) * DD;
        float4 v = *(const float4*)(row + l * 4);
        float s1 = warp_sum(v.x + v.y + v.z + v.w);
        float s2 = warp_sum(v.x * v.x + v.y * v.y + v.z * v.z + v.w * v.w);
        float m = s1 * (1.f / 128.f);
        float var = s2 * (1.f / 128.f) - m * m;
        float is = rsqrtf(var + 1e-5f);
        int c = l * 4;
        sln[w * 128 + c + 0] = (v.x - m) * is * gss[c + 0] + bss[c + 0];
        sln[w * 128 + c + 1] = (v.y - m) * is * gss[c + 1] + bss[c + 1];
        sln[w * 128 + c + 2] = (v.z - m) * is * gss[c + 2] + bss[c + 2];
        sln[w * 128 + c + 3] = (v.w - m) * is * gss[c + 3] + bss[c + 3];
    }
    __syncthreads();

    // phase 3: q = sln @ Wq^T + bq   (1024 outputs / 256 threads)
#pragma unroll
    for (int jj = 0; jj < 4; jj++) {
        int idx = tid + jj * 256;
        int s = idx >> 7, o = idx & 127;
        float acc = bqs[o];
        const float* wr = &Wqs[o * 129];
        const float* xr = &sln[s * 128];
#pragma unroll 16
        for (int i = 0; i < 128; i++) acc += wr[i] * xr[i];
        q_s[idx] = acc;
    }
    __syncthreads();

    // phase 4: main loop over this warp's 16 n's
    float qreg[8][4];
#pragma unroll
    for (int s = 0; s < 8; s++)
#pragma unroll
        for (int j = 0; j < 4; j++) qreg[s][j] = q_s[s * 128 + l * 4 + j];

    float acc[8][4];
#pragma unroll
    for (int s = 0; s < 8; s++)
#pragma unroll
        for (int j = 0; j < 4; j++) acc[s][j] = 0.f;
    float rsum[8];
#pragma unroll
    for (int s = 0; s < 8; s++) rsum[s] = 0.f;

    const int nbase = chunk * 128 + w * 16;
    const float* kb = g_k + (size_t)((b * NFF + frame) * NN) * DD;
    const float* vb = g_v + (size_t)((b * NFF + frame) * NN) * DD;
    float* attn_out = (fo >= 0)
        ? (outbuf + (size_t)BB * NFF * SS * DD + (size_t)((b * NFF + fo) * SS) * NN)
        : (float*)0;

#pragma unroll 1
    for (int nn = 0; nn < 16; nn++) {
        int n = nbase + nn;
        float4 kv = *(const float4*)(kb + (size_t)n * DD + l * 4);
        float p[8];
#pragma unroll
        for (int s = 0; s < 8; s++)
            p[s] = qreg[s][0] * kv.x + qreg[s][1] * kv.y +
                   qreg[s][2] * kv.z + qreg[s][3] * kv.w;
#pragma unroll
        for (int o = 16; o > 0; o >>= 1)
#pragma unroll
            for (int s = 0; s < 8; s++)
                p[s] += __shfl_xor_sync(0xffffffffu, p[s], o);

        // softmax over slots (all lanes redundantly)
        float d0[8], mx = -1e30f;
#pragma unroll
        for (int s = 0; s < 8; s++) { d0[s] = p[s] * SCALE_F; mx = fmaxf(mx, d0[s]); }
        float esum = 0.f, e[8];
#pragma unroll
        for (int s = 0; s < 8; s++) { e[s] = __expf(d0[s] - mx); esum += e[s]; }
        float inv = 1.f / esum;
        float a[8];
#pragma unroll
        for (int s = 0; s < 8; s++) { a[s] = e[s] * inv + EPS_F; rsum[s] += a[s]; }

        if (attn_out) {
#pragma unroll
            for (int s = 0; s < 8; s++)
                if (l == s) attn_out[s * NN + n] = a[s];
        }

        float4 vv = *(const float4*)(vb + (size_t)n * DD + l * 4);
#pragma unroll
        for (int s = 0; s < 8; s++) {
            acc[s][0] += a[s] * vv.x;
            acc[s][1] += a[s] * vv.y;
            acc[s][2] += a[s] * vv.z;
            acc[s][3] += a[s] * vv.w;
        }
    }

    // per-warp results -> smem
#pragma unroll
    for (int s = 0; s < 8; s++)
#pragma unroll
        for (int j = 0; j < 4; j++)
            wacc[w * 1024 + s * 128 + l * 4 + j] = acc[s][j];
    if (l == 0) {
#pragma unroll
        for (int s = 0; s < 8; s++) wrs[w * 8 + s] = rsum[s];
    }
    __syncthreads();

    // cross-warp reduce -> global partials (no atomics)
    {
        int o4 = tid * 4;
        float4 t = *(float4*)&wacc[o4];
#pragma unroll
        for (int ww = 1; ww < 8; ww++) {
            float4 u = *(float4*)&wacc[ww * 1024 + o4];
            t.x += u.x; t.y += u.y; t.z += u.z; t.w += u.w;
        }
        *(float4*)&g_upd_part[(b * NCHUNK + chunk) * 1024 + o4] = t;
        if (tid < 8) {
            float r = 0.f;
#pragma unroll
            for (int ww = 0; ww < 8; ww++) r += wrs[ww * 8 + tid];
            g_rs_part[(b * NCHUNK + chunk) * SS + tid] = r;
        }
    }
}

// ---------------- per-step: GRU + FF + outputs -----------------------------
__device__ __forceinline__ void sa_load_tile(float* dst, const float* __restrict__ src, int t) {
#pragma unroll
    for (int j = 0; j < 32; j++) {
        int idx4 = t + j * 128;            // 4096 float4
        int o = idx4 >> 5;
        int i0 = (idx4 & 31) * 4;
        float4 v = *(const float4*)(src + o * 128 + i0);
        dst[o * 129 + i0 + 0] = v.x;
        dst[o * 129 + i0 + 1] = v.y;
        dst[o * 129 + i0 + 2] = v.z;
        dst[o * 129 + i0 + 3] = v.w;
    }
}

__global__ __launch_bounds__(128, 1) void sa_gru_kernel(
    int cur, int fo, float* __restrict__ outbuf,
    const float* __restrict__ Wih, const float* __restrict__ Whh,
    const float* __restrict__ bih, const float* __restrict__ bhh,
    const float* __restrict__ W1, const float* __restrict__ b1,
    const float* __restrict__ W2, const float* __restrict__ b2,
    const float* __restrict__ gff, const float* __restrict__ bff) {
    extern __shared__ float sm[];
    float* T0  = sm;                 // [128][129]
    float* T1  = T0 + 128 * 129;     // [128][129]
    float* us  = T1 + 128 * 129;     // [128]
    float* hs  = us + 128;           // [128]
    float* lns = hs + 128;           // [128]
    float* f1s = lns + 128;          // [128]
    float* red = f1s + 128;          // [8]

    const int t = threadIdx.x;
    const int b = blockIdx.x >> 3, s = blockIdx.x & 7;
    const int wid = t >> 5;

    // u = (sum of chunk partials) / rowsum ; h = current slot
    float up = 0.f;
#pragma unroll
    for (int c = 0; c < NCHUNK; c++) up += g_upd_part[(b * NCHUNK + c) * 1024 + s * 128 + t];
    float rs = 0.f;
#pragma unroll
    for (int c = 0; c < NCHUNK; c++) rs += g_rs_part[(b * NCHUNK + c) * SS + s];
    float u = up / rs;
    float h = g_slots[cur][(b * SS + s) * DD + t];
    us[t] = u; hs[t] = h;

    float gi[3], gh[3];
#pragma unroll
    for (int p = 0; p < 3; p++) {
        __syncthreads();  // protect prior tile contents / us,hs visibility
        sa_load_tile(T0, Wih + p * 128 * 128, t);
        sa_load_tile(T1, Whh + p * 128 * 128, t);
        __syncthreads();
        float a = bih[p * 128 + t];
        float g = bhh[p * 128 + t];
        const float* w0 = &T0[t * 129];
        const float* w1 = &T1[t * 129];
#pragma unroll 16
        for (int i = 0; i < 128; i++) {
            a += w0[i] * us[i];
            g += w1[i] * hs[i];
        }
        gi[p] = a; gh[p] = g;
    }

    float r  = 1.f / (1.f + __expf(-(gi[0] + gh[0])));
    float z  = 1.f / (1.f + __expf(-(gi[1] + gh[1])));
    float nn = tanhf(gi[2] + r * gh[2]);
    float hp = (1.f - z) * nn + z * h;

    // LayerNorm(hp) across block of 128
    float s1 = warp_sum(hp);
    float s2 = warp_sum(hp * hp);
    __syncthreads();  // T0/T1 reads done before reuse below; also before red write
    if ((t & 31) == 0) { red[wid] = s1; red[4 + wid] = s2; }
    __syncthreads();
    s1 = red[0] + red[1] + red[2] + red[3];
    s2 = red[4] + red[5] + red[6] + red[7];
    float m = s1 * (1.f / 128.f);
    float var = s2 * (1.f / 128.f) - m * m;
    lns[t] = (hp - m) * rsqrtf(var + 1e-5f) * gff[t] + bff[t];

    sa_load_tile(T0, W1, t);
    sa_load_tile(T1, W2, t);
    __syncthreads();  // covers lns writes + tile loads

    float f1 = b1[t];
    {
        const float* w0 = &T0[t * 129];
#pragma unroll 16
        for (int i = 0; i < 128; i++) f1 += w0[i] * lns[i];
    }
    f1s[t] = fmaxf(f1, 0.f);
    __syncthreads();

    float f2 = b2[t];
    {
        const float* w1 = &T1[t * 129];
#pragma unroll 16
        for (int i = 0; i < 128; i++) f2 += w1[i] * f1s[i];
    }
    float out = hp + f2;
    g_slots[cur ^ 1][(b * SS + s) * DD + t] = out;
    if (fo >= 0)
        outbuf[(size_t)((b * NFF + fo) * SS + s) * DD + t] = out;
}

// ---------------------------------------------------------------------------
extern "C" void kernel_launch(void* const* d_in, const int* in_sizes, int n_in,
                              void* d_out, int out_size) {
    (void)in_sizes; (void)n_in; (void)out_size;
    const float* inputs     = (const float*)d_in[0];
    const float* slots_init = (const float*)d_in[1];
    const float* Wq  = (const float*)d_in[2];
    const float* bq  = (const float*)d_in[3];
    const float* Wk  = (const float*)d_in[4];
    const float* bk  = (const float*)d_in[5];
    const float* Wv  = (const float*)d_in[6];
    const float* bv  = (const float*)d_in[7];
    const float* W1  = (const float*)d_in[8];
    const float* b1  = (const float*)d_in[9];
    const float* W2  = (const float*)d_in[10];
    const float* b2  = (const float*)d_in[11];
    const float* Wih = (const float*)d_in[12];
    const float* Whh = (const float*)d_in[13];
    const float* bih = (const float*)d_in[14];
    const float* bhh = (const float*)d_in[15];
    const float* g_in  = (const float*)d_in[16];
    const float* be_in = (const float*)d_in[17];
    const float* g_sl  = (const float*)d_in[18];
    const float* be_sl = (const float*)d_in[19];
    const float* g_ff  = (const float*)d_in[20];
    const float* be_ff = (const float*)d_in[21];
    float* out = (float*)d_out;

    const int smem_kv   = (128 * 260 + 64 * 132 + 64 + 64 + 128 + 128 + 256) * 4; // 169472
    const int smem_attn = (128 * 129 + 128 * 3 + 1024 + 1024 + 8192 + 64) * 4;    // 108800
    const int smem_gru  = (2 * 128 * 129 + 4 * 128 + 8) * 4;                      // 134176

    cudaFuncSetAttribute(sa_kv_kernel,   cudaFuncAttributeMaxDynamicSharedMemorySize, smem_kv);
    cudaFuncSetAttribute(sa_attn_kernel, cudaFuncAttributeMaxDynamicSharedMemorySize, smem_attn);
    cudaFuncSetAttribute(sa_gru_kernel,  cudaFuncAttributeMaxDynamicSharedMemorySize, smem_gru);

    // init slots
    sa_init_kernel<<<(BB * SS * DD + 255) / 256, 256>>>(slots_init);

    // hoisted k/v projection for all frames
    sa_kv_kernel<<<(BB * NFF * NN) / 64, 256, smem_kv>>>(inputs, Wk, bk, Wv, bv, g_in, be_in);

    // sequential scan: warmup (it=0, frame 0, no output) + 16 recorded steps
    int cur = 0;
    for (int it = 0; it < 17; it++) {
        int frame = (it == 0) ? 0 : it - 1;
        int fo = it - 1;
        sa_attn_kernel<<<dim3(NCHUNK, BB), 256, smem_attn>>>(cur, frame, fo, out,
                                                             Wq, bq, g_sl, be_sl);
        sa_gru_kernel<<<BB * SS, 128, smem_gru>>>(cur, fo, out,
                                                  Wih, Whh, bih, bhh,
                                                  W1, b1, W2, b2, g_ff, be_ff);
        cur ^= 1;
    }
}

// round 11
// speedup vs baseline: 1.3005x; 1.3005x over previous
#include <cuda_runtime.h>
#include <math.h>

// Problem constants
#define BB 16
#define NFF 16
#define NN 1024
#define DD 128
#define SS 8
#define HH 128
#define NCH 16          // n-chunks for attention (64 n per chunk)

#define SCALE_F 0.08838834764831845f
#define EPS_F 1e-8f

typedef unsigned long long u64;

// ---------------- packed f32x2 helpers (Blackwell FFMA2 path) --------------
__device__ __forceinline__ u64 pack2(float lo, float hi) {
    u64 r;
    asm("mov.b64 %0, {%1, %2};" : "=l"(r)
        : "r"(__float_as_uint(lo)), "r"(__float_as_uint(hi)));
    return r;
}
__device__ __forceinline__ void unpack2(u64 v, float& lo, float& hi) {
    unsigned int a, b;
    asm("mov.b64 {%0, %1}, %2;" : "=r"(a), "=r"(b) : "l"(v));
    lo = __uint_as_float(a); hi = __uint_as_float(b);
}
__device__ __forceinline__ u64 ffma2(u64 a, u64 b, u64 c) {
    u64 d;
    asm("fma.rn.f32x2 %0, %1, %2, %3;" : "=l"(d) : "l"(a), "l"(b), "l"(c));
    return d;
}

// ---------------- async bulk-copy + mbarrier helpers -----------------------
__device__ __forceinline__ unsigned smem_u32(const void* p) {
    unsigned a;
    asm("{ .reg .u64 t; cvta.to.shared.u64 t, %1; cvt.u32.u64 %0, t; }"
        : "=r"(a) : "l"(p));
    return a;
}
__device__ __forceinline__ void mbar_init(unsigned mb, unsigned cnt) {
    asm volatile("mbarrier.init.shared.b64 [%0], %1;" :: "r"(mb), "r"(cnt) : "memory");
}
__device__ __forceinline__ void mbar_expect(unsigned mb, unsigned bytes) {
    asm volatile("mbarrier.arrive.expect_tx.shared.b64 _, [%0], %1;"
                 :: "r"(mb), "r"(bytes) : "memory");
}
__device__ __forceinline__ void bulk_cp(unsigned dst, const void* src,
                                        unsigned bytes, unsigned mb) {
    asm volatile("cp.async.bulk.shared::cta.global.mbarrier::complete_tx::bytes "
                 "[%0], [%1], %2, [%3];"
                 :: "r"(dst), "l"(src), "r"(bytes), "r"(mb) : "memory");
}
__device__ __forceinline__ void mbar_wait(unsigned mb, unsigned par) {
    unsigned done = 0;
    while (!done) {
        asm volatile("{\n\t.reg .pred p;\n\t"
                     "mbarrier.try_wait.parity.acquire.cta.shared::cta.b64 p, [%1], %2, 0x989680;\n\t"
                     "selp.b32 %0, 1, 0, p;\n\t}"
                     : "=r"(done) : "r"(mb), "r"(par) : "memory");
    }
}

// ---------------- scratch (device globals; no allocation allowed) ----------
__device__ float g_k[BB * NFF * NN * DD];                 // 134 MB
__device__ float g_v[BB * NFF * NN * DD];                 // 134 MB
__device__ float g_slots[2][BB * SS * DD];
__device__ float g_q[BB * SS * DD];                       // per-step queries
__device__ float g_upd_part[BB * NCH * SS * DD];          // per-(b,chunk) partial attn@v
__device__ float g_rs_part[BB * NCH * SS];                // per-(b,chunk) partial rowsums

// ---------------------------------------------------------------------------
__device__ __forceinline__ float warp_sum(float v) {
#pragma unroll
    for (int o = 16; o > 0; o >>= 1) v += __shfl_xor_sync(0xffffffffu, v, o);
    return v;
}

// ---------------- init: broadcast slots_init to all batches ----------------
__global__ void sa_init_kernel(const float* __restrict__ slots_init) {
    int idx = blockIdx.x * blockDim.x + threadIdx.x;
    if (idx < BB * SS * DD) g_slots[0][idx] = slots_init[idx & (SS * DD - 1)];
}

// ---------------- q0: q = LN_sl(slots[0]) @ Wq^T + bq ----------------------
// grid 128 (one per (b,s)), 128 threads. Wq via bulk-copy, skewed dot.
__global__ __launch_bounds__(128, 1) void sa_q0_kernel(
    const float* __restrict__ Wq, const float* __restrict__ bq,
    const float* __restrict__ gsl, const float* __restrict__ bsl) {
    extern __shared__ float sm[];
    float* T0  = sm + 32;                // [128*128] linear Wq
    float* lnq = T0 + 16384;             // [128]
    float* red = lnq + 128;              // [8]
    unsigned mb = smem_u32(sm);

    const int t = threadIdx.x, o = t, wid = t >> 5;
    const int blk = blockIdx.x;          // b*8+s

    if (t == 0) mbar_init(mb, 1);
    __syncthreads();
    if (t == 0) { mbar_expect(mb, 65536); bulk_cp(smem_u32(T0), Wq, 65536, mb); }

    float h = g_slots[0][blk * DD + o];
    float s1 = warp_sum(h), s2 = warp_sum(h * h);
    if ((t & 31) == 0) { red[wid] = s1; red[4 + wid] = s2; }
    __syncthreads();
    s1 = red[0] + red[1] + red[2] + red[3];
    s2 = red[4] + red[5] + red[6] + red[7];
    float m = s1 * (1.f / 128.f);
    float var = s2 * (1.f / 128.f) - m * m;
    lnq[o] = (h - m) * rsqrtf(var + 1e-5f) * gsl[o] + bsl[o];
    __syncthreads();

    mbar_wait(mb, 0);
    float q = bq[o];
#pragma unroll 8
    for (int i = 0; i < 128; i++) {
        int ii = (i + o) & 127;
        q += T0[o * 128 + ii] * lnq[ii];
    }
    g_q[blk * DD + o] = q;
}

// ---------------- kv projection: LN(x) @ [Wk^T | Wv^T] + bias --------------
// Block: 64 rows x 256 cols. 256 threads.
__global__ __launch_bounds__(256, 1) void sa_kv_kernel(
    const float* __restrict__ x,
    const float* __restrict__ Wk, const float* __restrict__ bk,
    const float* __restrict__ Wv, const float* __restrict__ bv,
    const float* __restrict__ gin, const float* __restrict__ bin) {
    extern __shared__ float sm[];
    float* Wt  = sm;                    // [128][260]
    float* Xs  = Wt + 128 * 260;        // [64][132]
    float* ms  = Xs + 64 * 132;
    float* iss = ms + 64;
    float* gs  = iss + 64;
    float* bs  = gs + 128;
    float* bias = bs + 128;

    const int tid = threadIdx.x;
    const int row0 = blockIdx.x * 64;

#pragma unroll 4
    for (int j = 0; j < 32; j++) {
        int idx4 = tid + j * 256;
        int outc = idx4 >> 5;
        int in0 = (idx4 & 31) * 4;
        const float* src = (outc < 128) ? (Wk + outc * 128 + in0)
                                        : (Wv + (outc - 128) * 128 + in0);
        float4 w = *(const float4*)src;
        Wt[(in0 + 0) * 260 + outc] = w.x;
        Wt[(in0 + 1) * 260 + outc] = w.y;
        Wt[(in0 + 2) * 260 + outc] = w.z;
        Wt[(in0 + 3) * 260 + outc] = w.w;
    }
    if (tid < 128) { gs[tid] = gin[tid]; bs[tid] = bin[tid]; }
    bias[tid] = (tid < 128) ? bk[tid] : bv[tid - 128];

#pragma unroll 2
    for (int j = 0; j < 8; j++) {
        int idx4 = tid + j * 256;
        int r = idx4 >> 5;
        int c4 = (idx4 & 31) * 4;
        float4 v = *(const float4*)(x + (size_t)(row0 + r) * DD + c4);
        *(float4*)&Xs[r * 132 + c4] = v;
    }
    __syncthreads();

    if (tid < 64) {
        float s1 = 0.f, s2 = 0.f;
#pragma unroll 16
        for (int i = 0; i < 128; i++) {
            float v = Xs[tid * 132 + i];
            s1 += v; s2 += v * v;
        }
        float m = s1 * (1.f / 128.f);
        float var = s2 * (1.f / 128.f) - m * m;
        ms[tid] = m;
        iss[tid] = rsqrtf(var + 1e-5f);
    }
    __syncthreads();

#pragma unroll 2
    for (int j = 0; j < 8; j++) {
        int idx4 = tid + j * 256;
        int r = idx4 >> 5;
        int c4 = (idx4 & 31) * 4;
        float m = ms[r], is = iss[r];
        float4 v = *(float4*)&Xs[r * 132 + c4];
        v.x = (v.x - m) * is * gs[c4 + 0] + bs[c4 + 0];
        v.y = (v.y - m) * is * gs[c4 + 1] + bs[c4 + 1];
        v.z = (v.z - m) * is * gs[c4 + 2] + bs[c4 + 2];
        v.w = (v.w - m) * is * gs[c4 + 3] + bs[c4 + 3];
        *(float4*)&Xs[r * 132 + c4] = v;
    }
    __syncthreads();

    const int tx = tid & 15, ty = tid >> 4;
    u64 acc2[4][8];
#pragma unroll
    for (int j2 = 0; j2 < 8; j2++) {
        u64 bpair = pack2(bias[tx * 16 + 2 * j2], bias[tx * 16 + 2 * j2 + 1]);
#pragma unroll
        for (int i = 0; i < 4; i++) acc2[i][j2] = bpair;
    }

#pragma unroll 8
    for (int k = 0; k < 128; k++) {
        u64 av2[4];
#pragma unroll
        for (int i = 0; i < 4; i++) {
            float a = Xs[(ty * 4 + i) * 132 + k];
            av2[i] = pack2(a, a);
        }
        u64 wv2[8];
#pragma unroll
        for (int g = 0; g < 4; g++) {
            ulonglong2 p = *(const ulonglong2*)&Wt[k * 260 + tx * 16 + g * 4];
            wv2[g * 2 + 0] = p.x;
            wv2[g * 2 + 1] = p.y;
        }
#pragma unroll
        for (int i = 0; i < 4; i++)
#pragma unroll
            for (int j2 = 0; j2 < 8; j2++)
                acc2[i][j2] = ffma2(av2[i], wv2[j2], acc2[i][j2]);
    }

#pragma unroll
    for (int i = 0; i < 4; i++) {
        int r = row0 + ty * 4 + i;
#pragma unroll
        for (int g = 0; g < 4; g++) {
            int c = tx * 16 + g * 4;
            float a0, a1, a2, a3;
            unpack2(acc2[i][2 * g + 0], a0, a1);
            unpack2(acc2[i][2 * g + 1], a2, a3);
            float4 o = make_float4(a0, a1, a2, a3);
            if (c < 128) *(float4*)&g_k[(size_t)r * DD + c] = o;
            else         *(float4*)&g_v[(size_t)r * DD + (c - 128)] = o;
        }
    }
}

// ---------------- per-step attention: dots + softmax + attn@v --------------
// grid (NCH=16, B=16), 256 threads. Block = (b, 64-n chunk). q precomputed.
__global__ __launch_bounds__(256, 2) void sa_attn_kernel(
    int frame, int fo, float* __restrict__ outbuf) {
    extern __shared__ float sm[];
    float* ks   = sm + 32;               // [64*128] linear
    float* vs   = ks + 8192;             // [64*128] linear
    float* qs   = vs + 8192;             // [8*128]
    float* ds   = qs + 1024;             // [8][64] dots
    float* as_  = ds + 512;              // [8][64] attn weights
    float* red2 = as_ + 512;             // [16]
    unsigned mb = smem_u32(sm);

    const int t = threadIdx.x;
    const int chunk = blockIdx.x, b = blockIdx.y;
    const int n0 = chunk * 64;

    const float* kb = g_k + (size_t)((b * NFF + frame) * NN + n0) * DD;
    const float* vb = g_v + (size_t)((b * NFF + frame) * NN + n0) * DD;

    if (t == 0) mbar_init(mb, 1);
    __syncthreads();
    if (t == 0) {
        mbar_expect(mb, 65536);
        bulk_cp(smem_u32(ks), kb, 32768, mb);
        bulk_cp(smem_u32(vs), vb, 32768, mb);
    }
    // load q via regular LDG concurrently with DMA
    ((float4*)qs)[t] = ((const float4*)(g_q + b * SS * DD))[t];
    __syncthreads();          // qs visible
    mbar_wait(mb, 0);

    // Phase B: dots. thread -> (n = t&63, slot pair sp = t>>6)
    {
        const int n = t & 63, sp = t >> 6;
        const int s0 = sp * 2, s1 = s0 + 1;
        float d0 = 0.f, d1 = 0.f;
#pragma unroll 8
        for (int i = 0; i < 128; i++) {
            int ii = (i + n) & 127;
            float kk = ks[n * 128 + ii];
            d0 += kk * qs[s0 * 128 + ii];
            d1 += kk * qs[s1 * 128 + ii];
        }
        ds[s0 * 64 + n] = d0;
        ds[s1 * 64 + n] = d1;
    }
    __syncthreads();

    // Phase C: softmax over slots for each n (threads 0..63)
    if (t < 64) {
        const int n = t;
        float d0[SS], mx = -1e30f;
#pragma unroll
        for (int s = 0; s < SS; s++) { d0[s] = ds[s * 64 + n] * SCALE_F; mx = fmaxf(mx, d0[s]); }
        float esum = 0.f, e[SS];
#pragma unroll
        for (int s = 0; s < SS; s++) { e[s] = __expf(d0[s] - mx); esum += e[s]; }
        float inv = 1.f / esum;
        float a[SS];
#pragma unroll
        for (int s = 0; s < SS; s++) a[s] = e[s] * inv + EPS_F;
#pragma unroll
        for (int s = 0; s < SS; s++) as_[s * 64 + n] = a[s];
        if (fo >= 0) {
            float* attn_out = outbuf + (size_t)BB * NFF * SS * DD
                              + (size_t)((b * NFF + fo) * SS) * NN;
#pragma unroll
            for (int s = 0; s < SS; s++) attn_out[s * NN + n0 + n] = a[s];
        }
        // per-slot rowsum partial (reduce over 64 n = 2 warps)
#pragma unroll
        for (int s = 0; s < SS; s++) {
            float r = warp_sum(a[s]);
            if ((t & 31) == 0) red2[(t >> 5) * 8 + s] = r;
        }
    }
    __syncthreads();
    if (t < 8) {
        g_rs_part[(b * NCH + chunk) * SS + t] = red2[t] + red2[8 + t];
    }

    // Phase D: upd[s][d] = sum_n a[s][n] * v[n][d].  thread -> (s=t>>5, d4=t&31)
    {
        const int s = t >> 5, d4 = t & 31;
        float4 acc = make_float4(0.f, 0.f, 0.f, 0.f);
#pragma unroll 8
        for (int n2 = 0; n2 < 64; n2++) {
            float aw = as_[s * 64 + n2];
            float4 vv = ((const float4*)vs)[n2 * 32 + d4];
            acc.x += aw * vv.x; acc.y += aw * vv.y;
            acc.z += aw * vv.z; acc.w += aw * vv.w;
        }
        ((float4*)&g_upd_part[(size_t)((b * NCH + chunk) * SS + s) * DD])[d4] = acc;
    }
}

// ---------------- per-step: GRU + FF + q-projection ------------------------
// grid 128 (one per (b,s)), 128 threads. Weights via cp.async.bulk, skewed dots.
__global__ __launch_bounds__(128, 1) void sa_gru_kernel(
    int cur, int fo, float* __restrict__ outbuf,
    const float* __restrict__ Wih, const float* __restrict__ Whh,
    const float* __restrict__ bih, const float* __restrict__ bhh,
    const float* __restrict__ W1, const float* __restrict__ b1,
    const float* __restrict__ W2, const float* __restrict__ b2,
    const float* __restrict__ gff, const float* __restrict__ bff,
    const float* __restrict__ Wq, const float* __restrict__ bq,
    const float* __restrict__ gsl, const float* __restrict__ bsl) {
    extern __shared__ float sm[];
    float* T0  = sm + 32;                // [128*128] linear tile
    float* T1  = T0 + 16384;             // [128*128]
    float* us  = T1 + 16384;             // [128]
    float* hs  = us + 128;               // [128]
    float* lns = hs + 128;               // [128]
    float* f1s = lns + 128;              // [128]
    float* red = f1s + 128;              // [8]
    unsigned mb = smem_u32(sm);

    const int t = threadIdx.x, o = t, wid = t >> 5;
    const int b = blockIdx.x >> 3, s = blockIdx.x & 7;

    if (t == 0) mbar_init(mb, 1);
    __syncthreads();
    // round 1: Wih_0 | Whh_0
    if (t == 0) {
        mbar_expect(mb, 131072);
        bulk_cp(smem_u32(T0), Wih, 65536, mb);
        bulk_cp(smem_u32(T1), Whh, 65536, mb);
    }

    // u = (sum of chunk partials) / rowsum ; h = current slot
    float up = 0.f;
#pragma unroll
    for (int c = 0; c < NCH; c++) up += g_upd_part[(size_t)((b * NCH + c) * SS + s) * DD + o];
    float rs = 0.f;
#pragma unroll
    for (int c = 0; c < NCH; c++) rs += g_rs_part[(b * NCH + c) * SS + s];
    float u = up / rs;
    float h = g_slots[cur][(b * SS + s) * DD + o];
    us[o] = u; hs[o] = h;
    __syncthreads();

    float gi[3], gh[3];
#pragma unroll 1
    for (int p = 0; p < 3; p++) {
        mbar_wait(mb, p & 1);
        float a = bih[p * 128 + o];
        float g = bhh[p * 128 + o];
#pragma unroll 8
        for (int i = 0; i < 128; i++) {
            int ii = (i + o) & 127;
            a += T0[o * 128 + ii] * us[ii];
            g += T1[o * 128 + ii] * hs[ii];
        }
        gi[p] = a; gh[p] = g;
        __syncthreads();                  // all reads of T0/T1 done
        if (p < 2 && t == 0) {
            mbar_expect(mb, 131072);
            bulk_cp(smem_u32(T0), Wih + (p + 1) * 16384, 65536, mb);
            bulk_cp(smem_u32(T1), Whh + (p + 1) * 16384, 65536, mb);
        }
    }

    float r  = 1.f / (1.f + __expf(-(gi[0] + gh[0])));
    float z  = 1.f / (1.f + __expf(-(gi[1] + gh[1])));
    float nn = tanhf(gi[2] + r * gh[2]);
    float hp = (1.f - z) * nn + z * h;

    // LayerNorm(hp) across the 128 threads
    float s1 = warp_sum(hp), s2 = warp_sum(hp * hp);
    if ((t & 31) == 0) { red[wid] = s1; red[4 + wid] = s2; }
    __syncthreads();
    s1 = red[0] + red[1] + red[2] + red[3];
    s2 = red[4] + red[5] + red[6] + red[7];
    float m = s1 * (1.f / 128.f);
    float var = s2 * (1.f / 128.f) - m * m;
    lns[o] = (hp - m) * rsqrtf(var + 1e-5f) * gff[o] + bff[o];
    __syncthreads();

    // round 4: W1 | W2   (parity 1)
    if (t == 0) {
        mbar_expect(mb, 131072);
        bulk_cp(smem_u32(T0), W1, 65536, mb);
        bulk_cp(smem_u32(T1), W2, 65536, mb);
    }
    mbar_wait(mb, 1);
    float f1 = b1[o];
#pragma unroll 8
    for (int i = 0; i < 128; i++) {
        int ii = (i + o) & 127;
        f1 += T0[o * 128 + ii] * lns[ii];
    }
    f1s[o] = fmaxf(f1, 0.f);
    __syncthreads();                      // T0 reads done, f1s visible

    // round 5: Wq (parity 0) — overlap with f2 compute
    if (t == 0) { mbar_expect(mb, 65536); bulk_cp(smem_u32(T0), Wq, 65536, mb); }

    float f2 = b2[o];
#pragma unroll 8
    for (int i = 0; i < 128; i++) {
        int ii = (i + o) & 127;
        f2 += T1[o * 128 + ii] * f1s[ii];
    }
    float out = hp + f2;
    g_slots[cur ^ 1][(b * SS + s) * DD + o] = out;
    if (fo >= 0)
        outbuf[(size_t)((b * NFF + fo) * SS + s) * DD + o] = out;

    // LayerNorm(out) with slot-LN params, then q = ln @ Wq^T + bq
    float w1s = warp_sum(out), w2s = warp_sum(out * out);
    __syncthreads();                      // red reuse safe
    if ((t & 31) == 0) { red[wid] = w1s; red[4 + wid] = w2s; }
    __syncthreads();
    w1s = red[0] + red[1] + red[2] + red[3];
    w2s = red[4] + red[5] + red[6] + red[7];
    float mq = w1s * (1.f / 128.f);
    float vq = w2s * (1.f / 128.f) - mq * mq;
    lns[o] = (out - mq) * rsqrtf(vq + 1e-5f) * gsl[o] + bsl[o];
    __syncthreads();

    mbar_wait(mb, 0);
    float q = bq[o];
#pragma unroll 8
    for (int i = 0; i < 128; i++) {
        int ii = (i + o) & 127;
        q += T0[o * 128 + ii] * lns[ii];
    }
    g_q[(b * SS + s) * DD + o] = q;
}

// ---------------------------------------------------------------------------
extern "C" void kernel_launch(void* const* d_in, const int* in_sizes, int n_in,
                              void* d_out, int out_size) {
    (void)in_sizes; (void)n_in; (void)out_size;
    const float* inputs     = (const float*)d_in[0];
    const float* slots_init = (const float*)d_in[1];
    const float* Wq  = (const float*)d_in[2];
    const float* bq  = (const float*)d_in[3];
    const float* Wk  = (const float*)d_in[4];
    const float* bk  = (const float*)d_in[5];
    const float* Wv  = (const float*)d_in[6];
    const float* bv  = (const float*)d_in[7];
    const float* W1  = (const float*)d_in[8];
    const float* b1  = (const float*)d_in[9];
    const float* W2  = (const float*)d_in[10];
    const float* b2  = (const float*)d_in[11];
    const float* Wih = (const float*)d_in[12];
    const float* Whh = (const float*)d_in[13];
    const float* bih = (const float*)d_in[14];
    const float* bhh = (const float*)d_in[15];
    const float* g_in  = (const float*)d_in[16];
    const float* be_in = (const float*)d_in[17];
    const float* g_sl  = (const float*)d_in[18];
    const float* be_sl = (const float*)d_in[19];
    const float* g_ff  = (const float*)d_in[20];
    const float* be_ff = (const float*)d_in[21];
    float* out = (float*)d_out;

    const int smem_kv   = (128 * 260 + 64 * 132 + 64 + 64 + 128 + 128 + 256) * 4; // 169472
    const int smem_q0   = (32 + 16384 + 128 + 8) * 4;                             // 66208
    const int smem_attn = (32 + 8192 + 8192 + 1024 + 512 + 512 + 16) * 4;         // 73920
    const int smem_gru  = (32 + 2 * 16384 + 4 * 128 + 8) * 4;                     // 133280

    cudaFuncSetAttribute(sa_kv_kernel,   cudaFuncAttributeMaxDynamicSharedMemorySize, smem_kv);
    cudaFuncSetAttribute(sa_q0_kernel,   cudaFuncAttributeMaxDynamicSharedMemorySize, smem_q0);
    cudaFuncSetAttribute(sa_attn_kernel, cudaFuncAttributeMaxDynamicSharedMemorySize, smem_attn);
    cudaFuncSetAttribute(sa_gru_kernel,  cudaFuncAttributeMaxDynamicSharedMemorySize, smem_gru);

    // init slots + initial q
    sa_init_kernel<<<(BB * SS * DD + 255) / 256, 256>>>(slots_init);
    sa_q0_kernel<<<BB * SS, 128, smem_q0>>>(Wq, bq, g_sl, be_sl);

    // hoisted k/v projection for all frames
    sa_kv_kernel<<<(BB * NFF * NN) / 64, 256, smem_kv>>>(inputs, Wk, bk, Wv, bv, g_in, be_in);

    // sequential scan: warmup (it=0, frame 0, no output) + 16 recorded steps
    int cur = 0;
    for (int it = 0; it < 17; it++) {
        int frame = (it == 0) ? 0 : it - 1;
        int fo = it - 1;
        sa_attn_kernel<<<dim3(NCH, BB), 256, smem_attn>>>(frame, fo, out);
        sa_gru_kernel<<<BB * SS, 128, smem_gru>>>(cur, fo, out,
                                                  Wih, Whh, bih, bhh,
                                                  W1, b1, W2, b2, g_ff, be_ff,
                                                  Wq, bq, g_sl, be_sl);
        cur ^= 1;
    }
}